// round 12
// baseline (speedup 1.0000x reference)
#include <cuda_runtime.h>
#include <math.h>

#define G     1920
#define P     22
#define NE    462
#define C5    152
#define T     120
#define BSZ   16
#define NCLS  17
#define DIMCAP 16
#define CO    272
#define CK    456
#define HS    152        // h row stride (floats)
#define QS    66         // q row base stride (floats)
#define QROW(r) ((r) * QS + ((((r) >> 2)) << 2))  // +4 per 4-row group -> rg banks {0,12,24,4,16,28}
#define TBC   15         // conv time tile -> grid = 16*8 = 128 = single wave
#define NTB   (T / TBC)  // 8
#define TXB   128        // extra k_gcn blocks for weight transpose
#define BT    128        // k_gcn block threads
#define CTH   680        // conv threads: 136 o-pairs x 5 groups of 3 steps

__device__ float g_pooled[G * C5];
__device__ float g_cwT[CK * CO];   // [(c*3+k)*CO + o]

typedef unsigned long long u64;

// ---- packed f32x2 helpers (Blackwell FFMA2) --------------------------------
__device__ __forceinline__ u64 dup2(float a) {
    u64 d;
    asm("mov.b64 %0, {%1, %1};" : "=l"(d) : "r"(__float_as_uint(a)));
    return d;
}
__device__ __forceinline__ void fma2(u64& acc, u64 a, u64 b) {
    asm("fma.rn.f32x2 %0, %1, %2, %0;" : "+l"(acc) : "l"(a), "l"(b));
}
__device__ __forceinline__ float2 unpk(u64 v) {
    unsigned lo, hi;
    asm("mov.b64 {%0, %1}, %2;" : "=r"(lo), "=r"(hi) : "l"(v));
    return make_float2(__uint_as_float(lo), __uint_as_float(hi));
}

// ---------------------------------------------------------------------------
// Phase A: q[r][c] = sum_i sA[r][i] * h[i][c]   (QROW layout)
// ---------------------------------------------------------------------------
__device__ __forceinline__ void phaseA(const float* __restrict__ sh,
                                       float* __restrict__ sq,
                                       const float* __restrict__ sA,
                                       int cin4, int tid)
{
    int ntask = P * cin4;
    for (int t = tid; t < ntask; t += BT) {
        int r  = t / cin4;
        int c4 = t - r * cin4;
        const float* sar = sA + r * P;
        const ulonglong2* hv = (const ulonglong2*)(sh + 4 * c4);
        u64 a0 = 0ULL, a1 = 0ULL;
        #pragma unroll
        for (int i = 0; i < P; i++) {
            u64 ad = dup2(sar[i]);
            ulonglong2 h2 = hv[i * (HS / 4)];
            fma2(a0, ad, h2.x);
            fma2(a1, ad, h2.y);
        }
        float* dst = sq + QROW(r) + 4 * c4;
        *(u64*)(dst)     = a0;
        *(u64*)(dst + 2) = a1;
    }
}

// ---------------------------------------------------------------------------
// Phase B: h'[r][o] = relu(b[o] + sum_c q[r][c]*W[c][o])
// 4 rows x 8 outputs per task, o8-major ordering, unroll 4 (R5 regime).
// ---------------------------------------------------------------------------
template<int CIN, int COUT>
__device__ __forceinline__ void phaseB(const float* __restrict__ sq,
                                       float* __restrict__ sh,
                                       const float* __restrict__ W,
                                       const float* __restrict__ b,
                                       int tid)
{
    const int NO8 = COUT / 8;
    const int NRG = 6;                 // ceil(22/4)
    const int NT  = NO8 * NRG;
    for (int t = tid; t < NT; t += BT) {
        int o8 = t / NRG;
        int rg = t - o8 * NRG;
        const float* q0 = sq + QROW(rg * 4);
        u64 acc[4][4];
        #pragma unroll
        for (int rr = 0; rr < 4; rr++)
            #pragma unroll
            for (int k = 0; k < 4; k++) acc[rr][k] = 0ULL;

        #pragma unroll 4
        for (int c = 0; c < CIN; c++) {
            u64 a0 = dup2(q0[0 * QS + c]);
            u64 a1 = dup2(q0[1 * QS + c]);
            u64 a2 = dup2(q0[2 * QS + c]);
            u64 a3 = dup2(q0[3 * QS + c]);
            const ulonglong2* wp = (const ulonglong2*)(W + c * COUT + o8 * 8);
            ulonglong2 w01 = wp[0];
            ulonglong2 w23 = wp[1];
            fma2(acc[0][0], a0, w01.x); fma2(acc[0][1], a0, w01.y);
            fma2(acc[0][2], a0, w23.x); fma2(acc[0][3], a0, w23.y);
            fma2(acc[1][0], a1, w01.x); fma2(acc[1][1], a1, w01.y);
            fma2(acc[1][2], a1, w23.x); fma2(acc[1][3], a1, w23.y);
            fma2(acc[2][0], a2, w01.x); fma2(acc[2][1], a2, w01.y);
            fma2(acc[2][2], a2, w23.x); fma2(acc[2][3], a2, w23.y);
            fma2(acc[3][0], a3, w01.x); fma2(acc[3][1], a3, w01.y);
            fma2(acc[3][2], a3, w23.x); fma2(acc[3][3], a3, w23.y);
        }
        float4 bA = *(const float4*)(b + o8 * 8);
        float4 bB = *(const float4*)(b + o8 * 8 + 4);
        #pragma unroll
        for (int rr = 0; rr < 4; rr++) {
            int r = rg * 4 + rr;
            if (r < P) {
                float2 v0 = unpk(acc[rr][0]);
                float2 v1 = unpk(acc[rr][1]);
                float2 v2 = unpk(acc[rr][2]);
                float2 v3 = unpk(acc[rr][3]);
                float4 sA4, sB4;
                sA4.x = fmaxf(v0.x + bA.x, 0.f);
                sA4.y = fmaxf(v0.y + bA.y, 0.f);
                sA4.z = fmaxf(v1.x + bA.z, 0.f);
                sA4.w = fmaxf(v1.y + bA.w, 0.f);
                sB4.x = fmaxf(v2.x + bB.x, 0.f);
                sB4.y = fmaxf(v2.y + bB.y, 0.f);
                sB4.z = fmaxf(v3.x + bB.z, 0.f);
                sB4.w = fmaxf(v3.y + bB.w, 0.f);
                float* dst = sh + r * HS + o8 * 8;
                *(float4*)(dst)     = sA4;
                *(float4*)(dst + 4) = sB4;
            }
        }
    }
}

// ---------------------------------------------------------------------------
// k_gcn: one 128-thread block per graph; tail blocks transpose conv weights
// ---------------------------------------------------------------------------
__global__ void __launch_bounds__(BT) k_gcn(
    const float* __restrict__ x,
    const float* __restrict__ edge_attr,
    const float* __restrict__ W1, const float* __restrict__ b1,
    const float* __restrict__ W2, const float* __restrict__ b2,
    const float* __restrict__ W3, const float* __restrict__ b3,
    const float* __restrict__ W4, const float* __restrict__ b4,
    const float* __restrict__ conv_w)
{
    if (blockIdx.x >= G) {
        int base = (blockIdx.x - G) * BT + threadIdx.x;
        for (int idx = base; idx < CK * CO; idx += TXB * BT) {
            int ck = idx / CO;
            int o  = idx - ck * CO;
            g_cwT[idx] = conv_w[o * CK + ck];
        }
        return;
    }

    __shared__ float sA[P * P];
    __shared__ float sh[P * HS];
    __shared__ float sq[24 * QS + 24];   // QROW layout, rows 22,23 = padding
    __shared__ float sdinv[P];

    const int g   = blockIdx.x;
    const int tid = threadIdx.x;

    // zero pad rows 22,23
    for (int e = tid; e < 2 * QS + 4; e += BT) sq[QROW(22) + e] = 0.f;

    // raw weighted adjacency Wm[i][j] into sh (temp), diag = 1
    for (int e = tid; e < NE; e += BT) {
        int i  = e / (P - 1);
        int jj = e - i * (P - 1);
        int j  = (jj < i) ? jj : jj + 1;
        sh[i * P + j] = edge_attr[(g * NE + e) * 5 + 4];
    }
    if (tid < P) sh[tid * P + tid] = 1.0f;
    __syncthreads();

    if (tid < P) {
        float d = 0.f;
        #pragma unroll
        for (int i = 0; i < P; i++) d += sh[i * P + tid];
        sdinv[tid] = (d > 0.f) ? rsqrtf(d) : 0.f;
    }
    __syncthreads();

    for (int e = tid; e < P * P; e += BT) {
        int j = e / P, i = e - j * P;
        sA[j * P + i] = sdinv[i] * sdinv[j] * sh[i * P + j];
    }
    __syncthreads();

    for (int e = tid; e < P * 16; e += BT) {
        int r = e >> 4, c = e & 15;
        sh[r * HS + c] = (c < 14) ? x[(g * P + r) * 14 + c] : 0.f;
    }
    __syncthreads();

    phaseA(sh, sq, sA, 4, tid);  __syncthreads();
    phaseB<14, 16>(sq, sh, W1, b1, tid); __syncthreads();

    phaseA(sh, sq, sA, 4, tid);  __syncthreads();
    phaseB<16, 32>(sq, sh, W2, b2, tid); __syncthreads();

    phaseA(sh, sq, sA, 8, tid);  __syncthreads();
    phaseB<32, 64>(sq, sh, W3, b3, tid); __syncthreads();

    phaseA(sh, sq, sA, 16, tid); __syncthreads();
    phaseB<64, 152>(sq, sh, W4, b4, tid); __syncthreads();

    if (tid < 38) {
        u64 s0 = 0ULL, s1 = 0ULL;
        u64 k22 = dup2(1.0f / 22.0f);
        const ulonglong2* hv = (const ulonglong2*)(sh + tid * 4);
        #pragma unroll
        for (int i = 0; i < P; i++) {
            ulonglong2 h2 = hv[i * (HS / 4)];
            fma2(s0, h2.x, k22);
            fma2(s1, h2.y, k22);
        }
        ulonglong2 o2; o2.x = s0; o2.y = s1;
        *(ulonglong2*)(g_pooled + g * C5 + tid * 4) = o2;
    }
}

// ---------------------------------------------------------------------------
// k_conv: block = (batch b, 15-t tile), 680 threads (136 o-pairs x 5 groups
// of 3 steps). grid = 128 = single wave. 6-deep register prefetch ring for
// L2-resident weights (18 LDGs in flight).
// ---------------------------------------------------------------------------
__global__ void __launch_bounds__(CTH) k_conv(
    const float* __restrict__ conv_b,
    const float* __restrict__ gamma,
    const float* __restrict__ beta,
    float* __restrict__ out)
{
    __shared__ float sp[(TBC + 2) * C5];
    __shared__ float s2[TBC * CO];
    __shared__ float sscale[TBC], sshift[TBC];

    const int b   = blockIdx.x / NTB;
    const int t0  = (blockIdx.x - b * NTB) * TBC;
    const int tid = threadIdx.x;

    if (tid < (TBC + 2) * (C5 / 4)) {
        int tt = tid / (C5 / 4);
        int c4 = tid - tt * (C5 / 4);
        int t  = t0 + tt - 1;
        float4 v = make_float4(0.f, 0.f, 0.f, 0.f);
        if (t >= 0 && t < T) v = *(const float4*)(g_pooled + (b * T + t) * C5 + c4 * 4);
        *(float4*)(sp + tt * C5 + c4 * 4) = v;
    }
    if (tid < TBC) {
        sscale[tid] = gamma[t0 + tid] * rsqrtf(1.0f + 0.001f);
        sshift[tid] = beta[t0 + tid];
    }
    __syncthreads();

    {
        const int op  = tid % 136;       // outputs 2op, 2op+1
        const int tg  = tid / 136;       // 0..4
        const int tt0 = tg * 3;

        u64 acc0 = 0ULL, acc1 = 0ULL, acc2 = 0ULL;
        const float* spb = sp + tt0 * C5;
        const u64* wb = (const u64*)g_cwT + op;   // element (c,k): wb[(3c+k)*136]

        // prefetch ring: 6 c-iterations ahead (18 LDGs in flight)
        u64 wbuf[6][3];
        {
            const u64* wp = wb;
            #pragma unroll
            for (int i = 0; i < 6; i++) {
                wbuf[i][0] = wp[0 * 136];
                wbuf[i][1] = wp[1 * 136];
                wbuf[i][2] = wp[2 * 136];
                wp += 3 * 136;
            }
        }
        const u64* wnext = wb + 18 * 136;

        #pragma unroll 6
        for (int c = 0; c < C5; c++) {
            int slot = c % 6;
            u64 w0 = wbuf[slot][0];
            u64 w1 = wbuf[slot][1];
            u64 w2 = wbuf[slot][2];
            if (c + 6 < C5) {
                wbuf[slot][0] = wnext[0 * 136];
                wbuf[slot][1] = wnext[1 * 136];
                wbuf[slot][2] = wnext[2 * 136];
            }
            wnext += 3 * 136;
            u64 pd0 = dup2(spb[0 * C5 + c]);
            u64 pd1 = dup2(spb[1 * C5 + c]);
            u64 pd2 = dup2(spb[2 * C5 + c]);
            u64 pd3 = dup2(spb[3 * C5 + c]);
            u64 pd4 = dup2(spb[4 * C5 + c]);
            fma2(acc0, pd0, w0); fma2(acc0, pd1, w1); fma2(acc0, pd2, w2);
            fma2(acc1, pd1, w0); fma2(acc1, pd2, w1); fma2(acc1, pd3, w2);
            fma2(acc2, pd2, w0); fma2(acc2, pd3, w1); fma2(acc2, pd4, w2);
        }

        float bx = conv_b[2 * op];
        float by = conv_b[2 * op + 1];
        u64 accs[3] = {acc0, acc1, acc2};
        #pragma unroll
        for (int j = 0; j < 3; j++) {
            int tt = tt0 + j;
            float sc = sscale[tt], sf = sshift[tt];
            float2 v = unpk(accs[j]);
            float ax = (v.x + bx) * sc + sf;
            float ay = (v.y + by) * sc + sf;
            float sx = __frcp_rn(1.0f + __expf(-ax)) - 0.5f;
            float sy = __frcp_rn(1.0f + __expf(-ay)) - 0.5f;
            *(float2*)(s2 + tt * CO + 2 * op) = make_float2(sx * sx, sy * sy);
        }
    }
    __syncthreads();

    if (tid < TBC * NCLS) {
        int tt = tid / NCLS;
        int n  = tid - tt * NCLS;
        float sum = 0.f;
        #pragma unroll
        for (int d = 0; d < DIMCAP; d++) sum += s2[tt * CO + d * NCLS + n];
        out[(b * T + t0 + tt) * NCLS + n] = sqrtf(sum * 0.25f);
    }
}

// ---------------------------------------------------------------------------
extern "C" void kernel_launch(void* const* d_in, const int* in_sizes, int n_in,
                              void* d_out, int out_size) {
    const float* x         = (const float*)d_in[0];
    const float* edge_attr = (const float*)d_in[3];
    const float* W1 = (const float*)d_in[4];
    const float* b1 = (const float*)d_in[5];
    const float* W2 = (const float*)d_in[6];
    const float* b2 = (const float*)d_in[7];
    const float* W3 = (const float*)d_in[8];
    const float* b3 = (const float*)d_in[9];
    const float* W4 = (const float*)d_in[10];
    const float* b4 = (const float*)d_in[11];
    const float* conv_w = (const float*)d_in[12];
    const float* conv_bb = (const float*)d_in[13];
    const float* gamma  = (const float*)d_in[14];
    const float* beta   = (const float*)d_in[15];
    float* out = (float*)d_out;

    k_gcn<<<G + TXB, BT>>>(x, edge_attr, W1, b1, W2, b2, W3, b3, W4, b4, conv_w);
    k_conv<<<BSZ * NTB, CTH>>>(conv_bb, gamma, beta, out);
}

// round 13
// speedup vs baseline: 1.0512x; 1.0512x over previous
#include <cuda_runtime.h>
#include <math.h>

#define G     1920
#define P     22
#define NE    462
#define C5    152
#define T     120
#define BSZ   16
#define NCLS  17
#define DIMCAP 16
#define CO    272
#define CK    456
#define HS    152        // h row stride (floats)
#define QS    66         // q row base stride (floats)
#define QROW(r) ((r) * QS + ((((r) >> 2)) << 2))  // +4 per 4-row group -> rg banks {0,12,24,4,16,28}
#define TBC   15         // conv time tile -> grid = 16*8 = 128 = single wave
#define NTB   (T / TBC)  // 8
#define TXB   128        // extra k_gcn blocks for weight transpose
#define BT    128        // k_gcn block threads
#define CTH   680        // conv threads: 136 o-pairs x 5 groups of 3 steps

__device__ float g_pooled[G * C5];
__device__ float g_cwT[CK * CO];   // [(c*3+k)*CO + o]

typedef unsigned long long u64;

// ---- packed f32x2 helpers (Blackwell FFMA2) --------------------------------
__device__ __forceinline__ u64 dup2(float a) {
    u64 d;
    asm("mov.b64 %0, {%1, %1};" : "=l"(d) : "r"(__float_as_uint(a)));
    return d;
}
__device__ __forceinline__ void fma2(u64& acc, u64 a, u64 b) {
    asm("fma.rn.f32x2 %0, %1, %2, %0;" : "+l"(acc) : "l"(a), "l"(b));
}
__device__ __forceinline__ float2 unpk(u64 v) {
    unsigned lo, hi;
    asm("mov.b64 {%0, %1}, %2;" : "=r"(lo), "=r"(hi) : "l"(v));
    return make_float2(__uint_as_float(lo), __uint_as_float(hi));
}

// ---------------------------------------------------------------------------
// Phase A: q[r][c] = sum_i sA[r][i] * h[i][c]   (QROW layout)
// ---------------------------------------------------------------------------
__device__ __forceinline__ void phaseA(const float* __restrict__ sh,
                                       float* __restrict__ sq,
                                       const float* __restrict__ sA,
                                       int cin4, int tid)
{
    int ntask = P * cin4;
    for (int t = tid; t < ntask; t += BT) {
        int r  = t / cin4;
        int c4 = t - r * cin4;
        const float* sar = sA + r * P;
        const ulonglong2* hv = (const ulonglong2*)(sh + 4 * c4);
        u64 a0 = 0ULL, a1 = 0ULL;
        #pragma unroll
        for (int i = 0; i < P; i++) {
            u64 ad = dup2(sar[i]);
            ulonglong2 h2 = hv[i * (HS / 4)];
            fma2(a0, ad, h2.x);
            fma2(a1, ad, h2.y);
        }
        float* dst = sq + QROW(r) + 4 * c4;
        *(u64*)(dst)     = a0;
        *(u64*)(dst + 2) = a1;
    }
}

// ---------------------------------------------------------------------------
// Phase B: h'[r][o] = relu(b[o] + sum_c q[r][c]*W[c][o])
// 4 rows x 8 outputs per task, o8-major ordering, unroll 4 (R5 regime).
// ---------------------------------------------------------------------------
template<int CIN, int COUT>
__device__ __forceinline__ void phaseB(const float* __restrict__ sq,
                                       float* __restrict__ sh,
                                       const float* __restrict__ W,
                                       const float* __restrict__ b,
                                       int tid)
{
    const int NO8 = COUT / 8;
    const int NRG = 6;                 // ceil(22/4)
    const int NT  = NO8 * NRG;
    for (int t = tid; t < NT; t += BT) {
        int o8 = t / NRG;
        int rg = t - o8 * NRG;
        const float* q0 = sq + QROW(rg * 4);
        u64 acc[4][4];
        #pragma unroll
        for (int rr = 0; rr < 4; rr++)
            #pragma unroll
            for (int k = 0; k < 4; k++) acc[rr][k] = 0ULL;

        #pragma unroll 4
        for (int c = 0; c < CIN; c++) {
            u64 a0 = dup2(q0[0 * QS + c]);
            u64 a1 = dup2(q0[1 * QS + c]);
            u64 a2 = dup2(q0[2 * QS + c]);
            u64 a3 = dup2(q0[3 * QS + c]);
            const ulonglong2* wp = (const ulonglong2*)(W + c * COUT + o8 * 8);
            ulonglong2 w01 = wp[0];
            ulonglong2 w23 = wp[1];
            fma2(acc[0][0], a0, w01.x); fma2(acc[0][1], a0, w01.y);
            fma2(acc[0][2], a0, w23.x); fma2(acc[0][3], a0, w23.y);
            fma2(acc[1][0], a1, w01.x); fma2(acc[1][1], a1, w01.y);
            fma2(acc[1][2], a1, w23.x); fma2(acc[1][3], a1, w23.y);
            fma2(acc[2][0], a2, w01.x); fma2(acc[2][1], a2, w01.y);
            fma2(acc[2][2], a2, w23.x); fma2(acc[2][3], a2, w23.y);
            fma2(acc[3][0], a3, w01.x); fma2(acc[3][1], a3, w01.y);
            fma2(acc[3][2], a3, w23.x); fma2(acc[3][3], a3, w23.y);
        }
        float4 bA = *(const float4*)(b + o8 * 8);
        float4 bB = *(const float4*)(b + o8 * 8 + 4);
        #pragma unroll
        for (int rr = 0; rr < 4; rr++) {
            int r = rg * 4 + rr;
            if (r < P) {
                float2 v0 = unpk(acc[rr][0]);
                float2 v1 = unpk(acc[rr][1]);
                float2 v2 = unpk(acc[rr][2]);
                float2 v3 = unpk(acc[rr][3]);
                float4 sA4, sB4;
                sA4.x = fmaxf(v0.x + bA.x, 0.f);
                sA4.y = fmaxf(v0.y + bA.y, 0.f);
                sA4.z = fmaxf(v1.x + bA.z, 0.f);
                sA4.w = fmaxf(v1.y + bA.w, 0.f);
                sB4.x = fmaxf(v2.x + bB.x, 0.f);
                sB4.y = fmaxf(v2.y + bB.y, 0.f);
                sB4.z = fmaxf(v3.x + bB.z, 0.f);
                sB4.w = fmaxf(v3.y + bB.w, 0.f);
                float* dst = sh + r * HS + o8 * 8;
                *(float4*)(dst)     = sA4;
                *(float4*)(dst + 4) = sB4;
            }
        }
    }
}

// ---------------------------------------------------------------------------
// k_gcn: one 128-thread block per graph; tail blocks transpose conv weights
// ---------------------------------------------------------------------------
__global__ void __launch_bounds__(BT) k_gcn(
    const float* __restrict__ x,
    const float* __restrict__ edge_attr,
    const float* __restrict__ W1, const float* __restrict__ b1,
    const float* __restrict__ W2, const float* __restrict__ b2,
    const float* __restrict__ W3, const float* __restrict__ b3,
    const float* __restrict__ W4, const float* __restrict__ b4,
    const float* __restrict__ conv_w)
{
    if (blockIdx.x >= G) {
        int base = (blockIdx.x - G) * BT + threadIdx.x;
        for (int idx = base; idx < CK * CO; idx += TXB * BT) {
            int ck = idx / CO;
            int o  = idx - ck * CO;
            g_cwT[idx] = conv_w[o * CK + ck];
        }
        return;
    }

    __shared__ float sA[P * P];
    __shared__ float sh[P * HS];
    __shared__ float sq[24 * QS + 24];   // QROW layout, rows 22,23 = padding
    __shared__ float sdinv[P];

    const int g   = blockIdx.x;
    const int tid = threadIdx.x;

    // zero pad rows 22,23
    for (int e = tid; e < 2 * QS + 4; e += BT) sq[QROW(22) + e] = 0.f;

    // raw weighted adjacency Wm[i][j] into sh (temp), diag = 1
    for (int e = tid; e < NE; e += BT) {
        int i  = e / (P - 1);
        int jj = e - i * (P - 1);
        int j  = (jj < i) ? jj : jj + 1;
        sh[i * P + j] = edge_attr[(g * NE + e) * 5 + 4];
    }
    if (tid < P) sh[tid * P + tid] = 1.0f;
    __syncthreads();

    if (tid < P) {
        float d = 0.f;
        #pragma unroll
        for (int i = 0; i < P; i++) d += sh[i * P + tid];
        sdinv[tid] = (d > 0.f) ? rsqrtf(d) : 0.f;
    }
    __syncthreads();

    for (int e = tid; e < P * P; e += BT) {
        int j = e / P, i = e - j * P;
        sA[j * P + i] = sdinv[i] * sdinv[j] * sh[i * P + j];
    }
    __syncthreads();

    for (int e = tid; e < P * 16; e += BT) {
        int r = e >> 4, c = e & 15;
        sh[r * HS + c] = (c < 14) ? x[(g * P + r) * 14 + c] : 0.f;
    }
    __syncthreads();

    phaseA(sh, sq, sA, 4, tid);  __syncthreads();
    phaseB<14, 16>(sq, sh, W1, b1, tid); __syncthreads();

    phaseA(sh, sq, sA, 4, tid);  __syncthreads();
    phaseB<16, 32>(sq, sh, W2, b2, tid); __syncthreads();

    phaseA(sh, sq, sA, 8, tid);  __syncthreads();
    phaseB<32, 64>(sq, sh, W3, b3, tid); __syncthreads();

    phaseA(sh, sq, sA, 16, tid); __syncthreads();
    phaseB<64, 152>(sq, sh, W4, b4, tid); __syncthreads();

    if (tid < 38) {
        u64 s0 = 0ULL, s1 = 0ULL;
        u64 k22 = dup2(1.0f / 22.0f);
        const ulonglong2* hv = (const ulonglong2*)(sh + tid * 4);
        #pragma unroll
        for (int i = 0; i < P; i++) {
            ulonglong2 h2 = hv[i * (HS / 4)];
            fma2(s0, h2.x, k22);
            fma2(s1, h2.y, k22);
        }
        ulonglong2 o2; o2.x = s0; o2.y = s1;
        *(ulonglong2*)(g_pooled + g * C5 + tid * 4) = o2;
    }
}

// ---------------------------------------------------------------------------
// k_conv: block = (batch b, 15-t tile), 680 threads. grid = 128 = single wave.
// 4-deep register prefetch ring (12 LDGs in flight), `c & 3` slot indexing.
// (R10 exact)
// ---------------------------------------------------------------------------
__global__ void __launch_bounds__(CTH) k_conv(
    const float* __restrict__ conv_b,
    const float* __restrict__ gamma,
    const float* __restrict__ beta,
    float* __restrict__ out)
{
    __shared__ float sp[(TBC + 2) * C5];
    __shared__ float s2[TBC * CO];
    __shared__ float sscale[TBC], sshift[TBC];

    const int b   = blockIdx.x / NTB;
    const int t0  = (blockIdx.x - b * NTB) * TBC;
    const int tid = threadIdx.x;

    if (tid < (TBC + 2) * (C5 / 4)) {
        int tt = tid / (C5 / 4);
        int c4 = tid - tt * (C5 / 4);
        int t  = t0 + tt - 1;
        float4 v = make_float4(0.f, 0.f, 0.f, 0.f);
        if (t >= 0 && t < T) v = *(const float4*)(g_pooled + (b * T + t) * C5 + c4 * 4);
        *(float4*)(sp + tt * C5 + c4 * 4) = v;
    }
    if (tid < TBC) {
        sscale[tid] = gamma[t0 + tid] * rsqrtf(1.0f + 0.001f);
        sshift[tid] = beta[t0 + tid];
    }
    __syncthreads();

    {
        const int op  = tid % 136;       // outputs 2op, 2op+1
        const int tg  = tid / 136;       // 0..4
        const int tt0 = tg * 3;

        u64 acc0 = 0ULL, acc1 = 0ULL, acc2 = 0ULL;
        const float* spb = sp + tt0 * C5;
        const u64* wb = (const u64*)g_cwT + op;   // element (c,k): wb[(3c+k)*136]

        // prefetch ring: 4 c-iterations ahead, 12 LDGs in flight
        u64 wbuf[4][3];
        #pragma unroll
        for (int i = 0; i < 4; i++) {
            wbuf[i][0] = wb[(3 * i + 0) * 136];
            wbuf[i][1] = wb[(3 * i + 1) * 136];
            wbuf[i][2] = wb[(3 * i + 2) * 136];
        }

        #pragma unroll 4
        for (int c = 0; c < C5; c++) {
            u64 w0 = wbuf[c & 3][0];
            u64 w1 = wbuf[c & 3][1];
            u64 w2 = wbuf[c & 3][2];
            int cn = c + 4;
            if (cn < C5) {
                wbuf[c & 3][0] = wb[(3 * cn + 0) * 136];
                wbuf[c & 3][1] = wb[(3 * cn + 1) * 136];
                wbuf[c & 3][2] = wb[(3 * cn + 2) * 136];
            }
            u64 pd0 = dup2(spb[0 * C5 + c]);
            u64 pd1 = dup2(spb[1 * C5 + c]);
            u64 pd2 = dup2(spb[2 * C5 + c]);
            u64 pd3 = dup2(spb[3 * C5 + c]);
            u64 pd4 = dup2(spb[4 * C5 + c]);
            fma2(acc0, pd0, w0); fma2(acc0, pd1, w1); fma2(acc0, pd2, w2);
            fma2(acc1, pd1, w0); fma2(acc1, pd2, w1); fma2(acc1, pd3, w2);
            fma2(acc2, pd2, w0); fma2(acc2, pd3, w1); fma2(acc2, pd4, w2);
        }

        float bx = conv_b[2 * op];
        float by = conv_b[2 * op + 1];
        u64 accs[3] = {acc0, acc1, acc2};
        #pragma unroll
        for (int j = 0; j < 3; j++) {
            int tt = tt0 + j;
            float sc = sscale[tt], sf = sshift[tt];
            float2 v = unpk(accs[j]);
            float ax = (v.x + bx) * sc + sf;
            float ay = (v.y + by) * sc + sf;
            float sx = __frcp_rn(1.0f + __expf(-ax)) - 0.5f;
            float sy = __frcp_rn(1.0f + __expf(-ay)) - 0.5f;
            *(float2*)(s2 + tt * CO + 2 * op) = make_float2(sx * sx, sy * sy);
        }
    }
    __syncthreads();

    if (tid < TBC * NCLS) {
        int tt = tid / NCLS;
        int n  = tid - tt * NCLS;
        float sum = 0.f;
        #pragma unroll
        for (int d = 0; d < DIMCAP; d++) sum += s2[tt * CO + d * NCLS + n];
        out[(b * T + t0 + tt) * NCLS + n] = sqrtf(sum * 0.25f);
    }
}

// ---------------------------------------------------------------------------
extern "C" void kernel_launch(void* const* d_in, const int* in_sizes, int n_in,
                              void* d_out, int out_size) {
    const float* x         = (const float*)d_in[0];
    const float* edge_attr = (const float*)d_in[3];
    const float* W1 = (const float*)d_in[4];
    const float* b1 = (const float*)d_in[5];
    const float* W2 = (const float*)d_in[6];
    const float* b2 = (const float*)d_in[7];
    const float* W3 = (const float*)d_in[8];
    const float* b3 = (const float*)d_in[9];
    const float* W4 = (const float*)d_in[10];
    const float* b4 = (const float*)d_in[11];
    const float* conv_w = (const float*)d_in[12];
    const float* conv_bb = (const float*)d_in[13];
    const float* gamma  = (const float*)d_in[14];
    const float* beta   = (const float*)d_in[15];
    float* out = (float*)d_out;

    k_gcn<<<G + TXB, BT>>>(x, edge_attr, W1, b1, W2, b2, W3, b3, W4, b4, conv_w);
    k_conv<<<BSZ * NTB, CTH>>>(conv_bb, gamma, beta, out);
}